// round 1
// baseline (speedup 1.0000x reference)
#include <cuda_runtime.h>
#include <cuda_bf16.h>

#define GSZ  32
#define NCTRL 68
#define MLS_EPS 1e-8f

// MLS deformation, 32x32 grid, 68 control points, per-batch.
// out[b][d][i][j], d=0 -> x-channel (col coord), d=1 -> y-channel (row coord).
//
// pf[c] = (int16)dp[c][1], (int16)dp[c][0]   (coord-swapped, truncated)
// qf[c] = (int16)sp[c][1], (int16)sp[c][0]
//
// t_x = (v - p*)^T M B_x + q*_x, M = inv(pTwp), B_x = sum_c w~ phat_c (qf_cx - q*_x)
__global__ __launch_bounds__(256, 4)
void mls_warp_kernel(const float* __restrict__ sp,
                     const float* __restrict__ dp,
                     float* __restrict__ out)
{
    __shared__ float4 ctrl[NCTRL];   // (pf_x, pf_y, qf_x, qf_y)

    const int b    = blockIdx.y;
    const int quad = blockIdx.x;     // which 256-pixel quadrant of the 1024-pixel grid
    const int tid  = threadIdx.x;

    if (tid < NCTRL) {
        const float* spb = sp + (size_t)b * (NCTRL * 2) + tid * 2;
        const float* dpb = dp + (size_t)b * (NCTRL * 2) + tid * 2;
        // coord swap + int16 truncation, exactly as the reference
        float pfx = (float)(short)dpb[1];
        float pfy = (float)(short)dpb[0];
        float qfx = (float)(short)spb[1];
        float qfy = (float)(short)spb[0];
        ctrl[tid] = make_float4(pfx, pfy, qfx, qfy);
    }
    __syncthreads();

    const int pix = quad * 256 + tid;          // 0..1023
    const float vx = (float)(pix & 31);        // column j
    const float vy = (float)(pix >> 5);        // row i

    // ---------- pass 1: sum of weights, weighted centroids ----------
    float sw = 0.f, spx_ = 0.f, spy_ = 0.f, sqx_ = 0.f, sqy_ = 0.f;
#pragma unroll 4
    for (int c = 0; c < NCTRL; ++c) {
        float4 k = ctrl[c];
        float dx = k.x - vx;
        float dy = k.y - vy;
        float d2 = fmaf(dx, dx, fmaf(dy, dy, MLS_EPS));
        float w  = 1.0f / d2;
        sw  += w;
        spx_ = fmaf(w, k.x, spx_);
        spy_ = fmaf(w, k.y, spy_);
        sqx_ = fmaf(w, k.z, sqx_);
        sqy_ = fmaf(w, k.w, sqy_);
    }
    const float inv_sw = 1.0f / sw;
    const float psx = spx_ * inv_sw, psy = spy_ * inv_sw;   // p*
    const float qsx = sqx_ * inv_sw, qsy = sqy_ * inv_sw;   // q*

    // ---------- pass 2: second moments of phat, cross moments with dq ----------
    // Cancellation-free (uses phat = pf - p* directly), matching reference numerics
    // at pixels that coincide with control points (w = 1e8 spikes).
    float a11 = 0.f, a12 = 0.f, a22 = 0.f;
    float bxx = 0.f, bxy = 0.f, byx = 0.f, byy = 0.f;
#pragma unroll 4
    for (int c = 0; c < NCTRL; ++c) {
        float4 k = ctrl[c];
        float dx = k.x - vx;
        float dy = k.y - vy;
        float d2 = fmaf(dx, dx, fmaf(dy, dy, MLS_EPS));
        float w  = inv_sw / d2;                // normalized weight w~
        float phx = k.x - psx;
        float phy = k.y - psy;
        float t1 = w * phx;
        float t2 = w * phy;
        a11 = fmaf(t1, phx, a11);
        a12 = fmaf(t1, phy, a12);
        a22 = fmaf(t2, phy, a22);
        float dqx = k.z - qsx;
        float dqy = k.w - qsy;
        bxx = fmaf(t1, dqx, bxx);
        bxy = fmaf(t2, dqx, bxy);
        byx = fmaf(t1, dqy, byx);
        byy = fmaf(t2, dqy, byy);
    }

    // ---------- closed-form 2x2 solve + output ----------
    const float det    = fmaf(a11, a22, -(a12 * a12));
    const float invdet = 1.0f / det;
    const float ux = vx - psx;
    const float uy = vy - psy;
    // r = (v - p*)^T M
    const float rx = (ux * a22 - uy * a12) * invdet;
    const float ry = (uy * a11 - ux * a12) * invdet;

    float tx = fmaf(rx, bxx, fmaf(ry, bxy, qsx));
    float ty = fmaf(rx, byx, fmaf(ry, byy, qsy));

    // out-of-range pixels are ZEROED (not clipped), per-channel
    if (!(tx >= 0.f) || tx > (float)(GSZ - 1)) tx = 0.f;
    if (!(ty >= 0.f) || ty > (float)(GSZ - 1)) ty = 0.f;
    // note: !(tx>=0) also maps NaN -> 0 deterministically; reference where(t<0,...)
    // keeps NaN, but degenerate dets do not occur with 68 random non-collinear controls.

    float* ob = out + (size_t)b * (2 * GSZ * GSZ);
    ob[pix]             = tx;   // channel 0 (x)
    ob[GSZ * GSZ + pix] = ty;   // channel 1 (y)
}

extern "C" void kernel_launch(void* const* d_in, const int* in_sizes, int n_in,
                              void* d_out, int out_size)
{
    const float* sp = (const float*)d_in[0];   // (B, 68, 2)
    const float* dp = (const float*)d_in[1];   // (B, 68, 2)
    float* out = (float*)d_out;                // (B, 2, 32, 32)

    int B = in_sizes[0] / (NCTRL * 2);         // 512 for this problem
    dim3 grid(4, B);
    mls_warp_kernel<<<grid, 256>>>(sp, dp, out);
}

// round 2
// speedup vs baseline: 1.7132x; 1.7132x over previous
#include <cuda_runtime.h>
#include <cuda_bf16.h>

#define GSZ   32
#define NCTRL 68
#define MLS_EPS 1e-8f

typedef unsigned long long u64;

// ---- packed f32x2 helpers (Blackwell sm_103a) ----
__device__ __forceinline__ u64 f2pack(float lo, float hi) {
    u64 r; asm("mov.b64 %0,{%1,%2};" : "=l"(r) : "f"(lo), "f"(hi)); return r;
}
__device__ __forceinline__ void f2unpack(u64 v, float& lo, float& hi) {
    asm("mov.b64 {%0,%1},%2;" : "=f"(lo), "=f"(hi) : "l"(v));
}
__device__ __forceinline__ u64 f2add(u64 a, u64 b) {
    u64 r; asm("add.rn.f32x2 %0,%1,%2;" : "=l"(r) : "l"(a), "l"(b)); return r;
}
__device__ __forceinline__ u64 f2mul(u64 a, u64 b) {
    u64 r; asm("mul.rn.f32x2 %0,%1,%2;" : "=l"(r) : "l"(a), "l"(b)); return r;
}
__device__ __forceinline__ u64 f2fma(u64 a, u64 b, u64 c) {
    u64 r; asm("fma.rn.f32x2 %0,%1,%2,%3;" : "=l"(r) : "l"(a), "l"(b), "l"(c)); return r;
}
__device__ __forceinline__ float frcp(float x) {
    float r; asm("rcp.approx.f32 %0,%1;" : "=f"(r) : "f"(x)); return r;
}

// Scalar epilogue: closed-form 2x2 solve from raw weighted moments.
//  m = Sigma w~ (pf - v)  ->  p* = v + m, ux = -mx
//  a11 = E[dx^2] - mx^2 ; a12 = E[dxdy] - mx my ; a22 = E[dy^2] - my^2
//  b.. = E[d_a * q_b] - m_a * q*_b
__device__ __forceinline__ void mls_finish(
    float sw, float sx, float sy,
    float sxx, float sxy, float syy,
    float sqx, float sqy,
    float sdxqx, float sdyqx, float sdxqy, float sdyqy,
    float* __restrict__ ob, int pix)
{
    const float isw = frcp(sw);
    const float mx  = sx * isw,  my  = sy * isw;
    const float a11 = fmaf(sxx, isw, -(mx * mx));
    const float a12 = fmaf(sxy, isw, -(mx * my));
    const float a22 = fmaf(syy, isw, -(my * my));
    const float qsx = sqx * isw, qsy = sqy * isw;
    const float bxx = fmaf(sdxqx, isw, -(mx * qsx));
    const float bxy = fmaf(sdyqx, isw, -(my * qsx));
    const float byx = fmaf(sdxqy, isw, -(mx * qsy));
    const float byy = fmaf(sdyqy, isw, -(my * qsy));

    const float det  = fmaf(a11, a22, -(a12 * a12));
    const float idet = 1.0f / det;
    const float ux = -mx, uy = -my;
    const float rx = (ux * a22 - uy * a12) * idet;
    const float ry = (uy * a11 - ux * a12) * idet;

    float tx = fmaf(rx, bxx, fmaf(ry, bxy, qsx));
    float ty = fmaf(rx, byx, fmaf(ry, byy, qsy));

    // out-of-range pixels are ZEROED (not clipped)
    if (!(tx >= 0.f) || tx > (float)(GSZ - 1)) tx = 0.f;
    if (!(ty >= 0.f) || ty > (float)(GSZ - 1)) ty = 0.f;

    ob[pix]               = tx;   // channel 0 (x)
    ob[GSZ * GSZ + pix]   = ty;   // channel 1 (y)
}

// 256 threads, each handles 2 pixels (pix, pix+256): same column vx, rows 8 apart.
// grid = (2, B): blockIdx.x selects upper/lower half of the 32x32 grid.
__global__ __launch_bounds__(256)
void mls_warp_kernel(const float* __restrict__ sp,
                     const float* __restrict__ dp,
                     float* __restrict__ out)
{
    // Per control: 4 pre-duplicated f32x2 words: (kx,kx)(ky,ky)(qx,qx)(qy,qy)
    __shared__ __align__(16) u64 cs[NCTRL * 4];

    const int b    = blockIdx.y;
    const int half = blockIdx.x;
    const int tid  = threadIdx.x;

    if (tid < NCTRL) {
        const float* spb = sp + (size_t)b * (NCTRL * 2) + tid * 2;
        const float* dpb = dp + (size_t)b * (NCTRL * 2) + tid * 2;
        // coord swap + int16 truncation, exactly as the reference
        float kx = (float)(short)dpb[1];
        float ky = (float)(short)dpb[0];
        float qx = (float)(short)spb[1];
        float qy = (float)(short)spb[0];
        cs[tid * 4 + 0] = f2pack(kx, kx);
        cs[tid * 4 + 1] = f2pack(ky, ky);
        cs[tid * 4 + 2] = f2pack(qx, qx);
        cs[tid * 4 + 3] = f2pack(qy, qy);
    }
    __syncthreads();

    const int pixA = half * 512 + tid;       // pixB = pixA + 256
    const float vx  = (float)(tid & 31);
    const float vyA = (float)(half * 16 + (tid >> 5));
    const float vyB = vyA + 8.0f;

    const u64 nvx2 = f2pack(-vx, -vx);
    const u64 nvy2 = f2pack(-vyA, -vyB);
    const u64 eps2 = f2pack(MLS_EPS, MLS_EPS);

    u64 sw = 0, Sx = 0, Sy = 0;
    u64 Sxx = 0, Sxy = 0, Syy = 0;
    u64 Sqx = 0, Sqy = 0;
    u64 Sdxqx = 0, Sdyqx = 0, Sdxqy = 0, Sdyqy = 0;

    const ulonglong2* csv = (const ulonglong2*)cs;
#pragma unroll 4
    for (int c = 0; c < NCTRL; ++c) {
        ulonglong2 u0 = csv[c * 2 + 0];      // (kx2, ky2)
        ulonglong2 u1 = csv[c * 2 + 1];      // (qx2, qy2)

        u64 dx = f2add(u0.x, nvx2);
        u64 dy = f2add(u0.y, nvy2);
        u64 d2 = f2fma(dx, dx, f2fma(dy, dy, eps2));

        float lo, hi;
        f2unpack(d2, lo, hi);
        u64 w = f2pack(frcp(lo), frcp(hi));

        u64 wdx = f2mul(w, dx);
        u64 wdy = f2mul(w, dy);

        sw  = f2add(sw, w);
        Sx  = f2add(Sx, wdx);
        Sy  = f2add(Sy, wdy);
        Sxx = f2fma(wdx, dx, Sxx);
        Sxy = f2fma(wdx, dy, Sxy);
        Syy = f2fma(wdy, dy, Syy);
        Sqx = f2fma(w, u1.x, Sqx);
        Sqy = f2fma(w, u1.y, Sqy);
        Sdxqx = f2fma(wdx, u1.x, Sdxqx);
        Sdyqx = f2fma(wdy, u1.x, Sdyqx);
        Sdxqy = f2fma(wdx, u1.y, Sdxqy);
        Sdyqy = f2fma(wdy, u1.y, Sdyqy);
    }

    float* ob = out + (size_t)b * (2 * GSZ * GSZ);

    float swl, swh, sxl, sxh, syl, syh;
    float sxxl, sxxh, sxyl, sxyh, syyl, syyh;
    float sqxl, sqxh, sqyl, sqyh;
    float s1l, s1h, s2l, s2h, s3l, s3h, s4l, s4h;
    f2unpack(sw, swl, swh);   f2unpack(Sx, sxl, sxh);   f2unpack(Sy, syl, syh);
    f2unpack(Sxx, sxxl, sxxh); f2unpack(Sxy, sxyl, sxyh); f2unpack(Syy, syyl, syyh);
    f2unpack(Sqx, sqxl, sqxh); f2unpack(Sqy, sqyl, sqyh);
    f2unpack(Sdxqx, s1l, s1h); f2unpack(Sdyqx, s2l, s2h);
    f2unpack(Sdxqy, s3l, s3h); f2unpack(Sdyqy, s4l, s4h);

    mls_finish(swl, sxl, syl, sxxl, sxyl, syyl, sqxl, sqyl, s1l, s2l, s3l, s4l, ob, pixA);
    mls_finish(swh, sxh, syh, sxxh, sxyh, syyh, sqxh, sqyh, s1h, s2h, s3h, s4h, ob, pixA + 256);
}

extern "C" void kernel_launch(void* const* d_in, const int* in_sizes, int n_in,
                              void* d_out, int out_size)
{
    const float* sp = (const float*)d_in[0];   // (B, 68, 2)
    const float* dp = (const float*)d_in[1];   // (B, 68, 2)
    float* out = (float*)d_out;                // (B, 2, 32, 32)

    int B = in_sizes[0] / (NCTRL * 2);         // 512 for this problem
    dim3 grid(2, B);
    mls_warp_kernel<<<grid, 256>>>(sp, dp, out);
}